// round 2
// baseline (speedup 1.0000x reference)
#include <cuda_runtime.h>
#include <cuda_bf16.h>
#include <math.h>

#define BB 4
#define TT 2048
#define DD 1024
#define HH 16
#define KK 64
#define BT (BB*TT)          /* 8192 tokens */
#define SCH 32              /* our chunk length (numerically safe in fp32) */
#define NCH (TT/SCH)        /* 64 chunks per sequence */
#define NBH (BB*HH)         /* 64 (batch,head) pairs */
#define LOGMIN (-5.2983174f) /* log(0.005) */
#define LN_EPS 6.4e-4f       /* 1e-5 * 8^2 */

// ---------------- scratch (static device arrays; no runtime allocation) ----
static __device__ float g_xx   [BT*DD];
static __device__ float g_xmix [BT*DD];
static __device__ float g_xxx  [BT*160];
static __device__ float g_xw   [BT*DD];
static __device__ float g_xk   [BT*DD];
static __device__ float g_xv   [BT*DD];
static __device__ float g_xr   [BT*DD];
static __device__ float g_xg   [BT*DD];
static __device__ float g_r    [BT*DD];
static __device__ float g_k    [BT*DD];
static __device__ float g_v    [BT*DD];
static __device__ float g_gate [BT*DD];
static __device__ float g_w    [BT*DD];
static __device__ float g_t1   [BT*64];
static __device__ float g_rw   [BT*DD];
static __device__ float g_att  [BT*DD];
static __device__ float g_yn   [BT*DD];
static __device__ float g_wkvc [NBH*NCH*KK*KK];
static __device__ float g_states[NBH*NCH*KK*KK];
static __device__ float g_expws[NBH*NCH*KK];

// ---------------- kernel 1: token shift + mix input ------------------------
__global__ void prep_kernel(const float* __restrict__ x, const float* __restrict__ tmx,
                            float* __restrict__ xx, float* __restrict__ xmix)
{
    size_t idx = (size_t)blockIdx.x * 256 + threadIdx.x;
    int d = (int)(idx & (DD - 1));
    int t = (int)((idx >> 10) & (TT - 1));   // DD = 2^10
    float xv = x[idx];
    float prev = (t == 0) ? 0.f : x[idx - DD];
    float xxv = prev - xv;
    xx[idx] = xxv;
    xmix[idx] = xv + xxv * tmx[d];
}

// ---------------- generic tiled fp32 GEMM with fused epilogues --------------
// C[M,N] = A[M,K] @ B[K,N].  EPI: 0 none, 1 tanh, 2 silu, 3 -exp(bias[n]+v)
template<int EPI>
__global__ __launch_bounds__(256) void gemm64(
    const float* __restrict__ A, const float* __restrict__ B,
    float* __restrict__ C, int M, int N, int Kd, const float* __restrict__ bias)
{
    __shared__ float As[16][68];   // [k][m], padded
    __shared__ float Bs[16][64];   // [k][n]
    int tid = threadIdx.x;
    int tx = tid & 15, ty = tid >> 4;
    int m0 = blockIdx.y << 6, n0 = blockIdx.x << 6;
    float acc[4][4];
#pragma unroll
    for (int i = 0; i < 4; i++)
#pragma unroll
        for (int j = 0; j < 4; j++) acc[i][j] = 0.f;

    int ar = tid >> 2, ac = (tid & 3) << 2;
    int br = tid >> 4, bc = (tid & 15) << 2;

    for (int k0 = 0; k0 < Kd; k0 += 16) {
        float4 a4 = *(const float4*)(A + (size_t)(m0 + ar) * Kd + k0 + ac);
        As[ac + 0][ar] = a4.x; As[ac + 1][ar] = a4.y;
        As[ac + 2][ar] = a4.z; As[ac + 3][ar] = a4.w;
        int gn = n0 + bc;
        float4 b4;
        if (gn + 3 < N) {
            b4 = *(const float4*)(B + (size_t)(k0 + br) * N + gn);
        } else {
            b4.x = (gn + 0 < N) ? B[(size_t)(k0 + br) * N + gn + 0] : 0.f;
            b4.y = (gn + 1 < N) ? B[(size_t)(k0 + br) * N + gn + 1] : 0.f;
            b4.z = (gn + 2 < N) ? B[(size_t)(k0 + br) * N + gn + 2] : 0.f;
            b4.w = (gn + 3 < N) ? B[(size_t)(k0 + br) * N + gn + 3] : 0.f;
        }
        *(float4*)&Bs[br][bc] = b4;
        __syncthreads();
#pragma unroll
        for (int kk = 0; kk < 16; kk++) {
            float4 av = *(float4*)&As[kk][ty << 2];
            float4 bv = *(float4*)&Bs[kk][tx << 2];
            float aa[4] = {av.x, av.y, av.z, av.w};
            float bb[4] = {bv.x, bv.y, bv.z, bv.w};
#pragma unroll
            for (int i = 0; i < 4; i++)
#pragma unroll
                for (int j = 0; j < 4; j++) acc[i][j] += aa[i] * bb[j];
        }
        __syncthreads();
    }
#pragma unroll
    for (int i = 0; i < 4; i++) {
        int m = m0 + (ty << 2) + i;
#pragma unroll
        for (int j = 0; j < 4; j++) {
            int n = n0 + (tx << 2) + j;
            if (n < N) {
                float val = acc[i][j];
                if (EPI == 1) val = tanhf(val);
                else if (EPI == 2) val = val / (1.f + expf(-val));
                else if (EPI == 3) val = -expf(bias[n] + val);
                C[(size_t)m * N + n] = val;
            }
        }
    }
}

// ---------------- kernel 3: 5-branch LoRA mix -------------------------------
__global__ __launch_bounds__(256) void branch_mix(
    const float* __restrict__ x, const float* __restrict__ xx,
    const float* __restrict__ xxx, const float* __restrict__ W2,
    const float* __restrict__ tmw, const float* __restrict__ tmk,
    const float* __restrict__ tmv, const float* __restrict__ tmr,
    const float* __restrict__ tmg,
    float* __restrict__ xw, float* __restrict__ xk, float* __restrict__ xv,
    float* __restrict__ xr, float* __restrict__ xg)
{
    __shared__ float sx[16][160];
    int tid = threadIdx.x;
    int t0 = blockIdx.x * 16;
    int d  = blockIdx.y * 256 + tid;
    for (int e = tid; e < 16 * 160; e += 256) {
        int tok = e / 160, c = e - tok * 160;
        sx[tok][c] = xxx[(size_t)(t0 + tok) * 160 + c];
    }
    __syncthreads();
    float m[5][16];
#pragma unroll
    for (int f = 0; f < 5; f++)
#pragma unroll
        for (int tok = 0; tok < 16; tok++) m[f][tok] = 0.f;
    for (int f = 0; f < 5; f++) {
        for (int i = 0; i < 32; i++) {
            float wv = W2[(size_t)(f * 32 + i) * DD + d];
#pragma unroll
            for (int tok = 0; tok < 16; tok++) m[f][tok] += sx[tok][f * 32 + i] * wv;
        }
    }
    float t_w = tmw[d], t_k = tmk[d], t_v = tmv[d], t_r = tmr[d], t_g = tmg[d];
    for (int tok = 0; tok < 16; tok++) {
        size_t gi = (size_t)(t0 + tok) * DD + d;
        float xv_ = x[gi], xxv = xx[gi];
        xw[gi] = xv_ + xxv * (t_w + m[0][tok]);
        xk[gi] = xv_ + xxv * (t_k + m[1][tok]);
        xv[gi] = xv_ + xxv * (t_v + m[2][tok]);
        xr[gi] = xv_ + xxv * (t_r + m[3][tok]);
        xg[gi] = xv_ + xxv * (t_g + m[4][tok]);
    }
}

// ---------------- WKV pass 1: per-chunk intra work + summaries --------------
__global__ __launch_bounds__(256) void wkv_chunk(
    const float* __restrict__ r, const float* __restrict__ k,
    const float* __restrict__ v, const float* __restrict__ w,
    const float* __restrict__ u,
    float* __restrict__ rw, float* __restrict__ att,
    float* __restrict__ wkvc, float* __restrict__ expws)
{
    __shared__ float sr [SCH][KK + 1];
    __shared__ float sk [SCH][KK + 1];
    __shared__ float sv [SCH][KK + 1];
    __shared__ float swl[SCH][KK + 1];   // wlog, later overwritten with kw
    __shared__ float swc[SCH][KK + 1];   // inclusive cumsum; later reused for A
    __shared__ float soff[KK];
    __shared__ float sdiag[SCH];
    float* sA = &swc[0][0];              // 1024 floats inside swc region

    int tid = threadIdx.x;
    int bid = blockIdx.x;
    int n = bid & (NCH - 1);
    int h = (bid / NCH) & (HH - 1);
    int b = bid / (NCH * HH);
    size_t base = ((size_t)(b * TT + n * SCH)) * DD + h * KK;

    for (int e = tid; e < SCH * KK; e += 256) {
        int t = e >> 6, c = e & 63;
        size_t gi = base + (size_t)t * DD + c;
        sr [t][c] = r[gi];
        sk [t][c] = k[gi];
        sv [t][c] = v[gi];
        swl[t][c] = fmaxf(w[gi], LOGMIN);
    }
    __syncthreads();
    if (tid < KK) {
        float c = 0.f;
        for (int t = 0; t < SCH; t++) { c += swl[t][tid]; swc[t][tid] = c; }
        expws[(size_t)bid * KK + tid] = expf(c);
        soff[tid] = swc[16][tid] - swl[16][tid];   // shifted at chunk center
    }
    __syncthreads();
    if (tid < SCH) {   // diagonal term: sum_k r*u*k
        float acc = 0.f;
        for (int c = 0; c < KK; c++) acc += sr[tid][c] * u[h * KK + c] * sk[tid][c];
        sdiag[tid] = acc;
    }
    __syncthreads();
    // elementwise transforms (overwrite sr->r_decay, sk->k_inv, swl->kw); emit rw
    for (int e = tid; e < SCH * KK; e += 256) {
        int t = e >> 6, c = e & 63;
        float wl = swl[t][c], wc = swc[t][c];
        float shft = wc - wl;                 // exclusive cumsum
        float off  = soff[c];
        float ws   = swc[SCH - 1][c];
        float rv = sr[t][c], kv = sk[t][c];
        rw[base + (size_t)t * DD + c] = rv * expf(shft);       // r * w_intra
        sr [t][c] = rv * expf(shft - off);                     // r_decay
        sk [t][c] = kv * expf(off - wc);                       // k_inv
        swl[t][c] = kv * expf(ws - wc);                        // k * w_inter
    }
    __syncthreads();
    // A = tril(r_decay @ k_inv^T, -1) + diag  (32x32) — goes into swc region
    for (int e = tid; e < SCH * SCH; e += 256) {
        int i = e >> 5, j = e & 31;
        float acc = 0.f;
        if (i > j) {
            for (int c = 0; c < KK; c++) acc += sr[i][c] * sk[j][c];
        } else if (i == j) acc = sdiag[i];
        sA[e] = acc;
    }
    __syncthreads();
    // intra-chunk output: out = A @ v
    for (int e = tid; e < SCH * KK; e += 256) {
        int t = e >> 6, vv = e & 63;
        float acc = 0.f;
        for (int j = 0; j <= t; j++) acc += sA[t * SCH + j] * sv[j][vv];
        att[base + (size_t)t * DD + vv] = acc;
    }
    // chunk summary: wkv_c[k][v] = sum_t kw[t][k]*v[t][v]
    for (int e = tid; e < KK * KK; e += 256) {
        int c = e >> 6, vv = e & 63;
        float acc = 0.f;
        for (int t = 0; t < SCH; t++) acc += swl[t][c] * sv[t][vv];
        wkvc[(size_t)bid * (KK * KK) + e] = acc;
    }
}

// ---------------- WKV pass 2: serial scan over chunks -----------------------
__global__ __launch_bounds__(1024) void wkv_scan(
    const float* __restrict__ wkvc, const float* __restrict__ expws,
    float* __restrict__ states)
{
    int bh = blockIdx.x;
    int tid = threadIdx.x;
    int c  = tid >> 4;
    int v0 = (tid & 15) << 2;
    float s0 = 0.f, s1 = 0.f, s2 = 0.f, s3 = 0.f;
    size_t eb = (size_t)bh * NCH * KK;
    size_t sb = (size_t)bh * NCH * KK * KK + (size_t)c * KK + v0;
    for (int n = 0; n < NCH; n++) {
        float wd = expws[eb + (size_t)n * KK + c];
        size_t o = sb + (size_t)n * KK * KK;
        float4 st; st.x = s0; st.y = s1; st.z = s2; st.w = s3;
        *(float4*)(states + o) = st;                // state BEFORE chunk n
        float4 wc4 = *(const float4*)(wkvc + o);
        s0 = s0 * wd + wc4.x; s1 = s1 * wd + wc4.y;
        s2 = s2 * wd + wc4.z; s3 = s3 * wd + wc4.w;
    }
}

// ---------------- WKV pass 3: apply carried state ---------------------------
__global__ __launch_bounds__(256) void wkv_state_out(
    const float* __restrict__ rw, const float* __restrict__ states,
    float* __restrict__ att)
{
    __shared__ float sst[KK][KK];
    __shared__ float srw[SCH][KK];
    int tid = threadIdx.x, bid = blockIdx.x;
    int n = bid & (NCH - 1);
    int h = (bid / NCH) & (HH - 1);
    int b = bid / (NCH * HH);
    size_t base = ((size_t)(b * TT + n * SCH)) * DD + h * KK;
    size_t stb = (size_t)bid * (KK * KK);
    for (int e = tid; e < KK * KK; e += 256) sst[e >> 6][e & 63] = states[stb + e];
    for (int e = tid; e < SCH * KK; e += 256) {
        int t = e >> 6, c = e & 63;
        srw[t][c] = rw[base + (size_t)t * DD + c];
    }
    __syncthreads();
    for (int e = tid; e < SCH * KK; e += 256) {
        int t = e >> 6, vv = e & 63;
        float acc = 0.f;
#pragma unroll 8
        for (int c = 0; c < KK; c++) acc += srw[t][c] * sst[c][vv];
        size_t gi = base + (size_t)t * DD + vv;
        att[gi] += acc;
    }
}

// ---------------- group-norm (per head) + gate ------------------------------
__global__ __launch_bounds__(256) void gnorm_gate(
    const float* __restrict__ att, const float* __restrict__ gate,
    const float* __restrict__ lnw, const float* __restrict__ lnb,
    float* __restrict__ y)
{
    int token = blockIdx.x, tid = threadIdx.x;
    size_t base = (size_t)token * DD + tid * 4;
    float4 v4 = *(const float4*)(att + base);
    float s  = v4.x + v4.y + v4.z + v4.w;
    float ss = v4.x * v4.x + v4.y * v4.y + v4.z * v4.z + v4.w * v4.w;
#pragma unroll
    for (int o = 1; o < 16; o <<= 1) {
        s  += __shfl_xor_sync(0xffffffffu, s,  o);
        ss += __shfl_xor_sync(0xffffffffu, ss, o);
    }
    float mean = s * (1.f / KK);
    float var  = ss * (1.f / KK) - mean * mean;
    float rstd = rsqrtf(var + LN_EPS);
    float4 g4 = *(const float4*)(gate + base);
    float4 w4 = *(const float4*)(lnw + tid * 4);
    float4 b4 = *(const float4*)(lnb + tid * 4);
    float4 o4;
    o4.x = ((v4.x - mean) * rstd * w4.x + b4.x) * g4.x;
    o4.y = ((v4.y - mean) * rstd * w4.y + b4.y) * g4.y;
    o4.z = ((v4.z - mean) * rstd * w4.z + b4.z) * g4.z;
    o4.w = ((v4.w - mean) * rstd * w4.w + b4.w) * g4.w;
    *(float4*)(y + base) = o4;
}

// ---------------- launch ----------------------------------------------------
extern "C" void kernel_launch(void* const* d_in, const int* in_sizes, int n_in,
                              void* d_out, int out_size)
{
    const float* x     = (const float*)d_in[0];
    const float* tmx   = (const float*)d_in[1];
    const float* tmw   = (const float*)d_in[2];
    const float* tmk   = (const float*)d_in[3];
    const float* tmv   = (const float*)d_in[4];
    const float* tmr   = (const float*)d_in[5];
    const float* tmg   = (const float*)d_in[6];
    const float* w1    = (const float*)d_in[7];
    const float* w2    = (const float*)d_in[8];
    const float* tdec  = (const float*)d_in[9];
    const float* dw1   = (const float*)d_in[10];
    const float* dw2   = (const float*)d_in[11];
    const float* faaaa = (const float*)d_in[12];
    const float* Wr    = (const float*)d_in[13];
    const float* Wk    = (const float*)d_in[14];
    const float* Wv    = (const float*)d_in[15];
    const float* Wg    = (const float*)d_in[16];
    const float* Wo    = (const float*)d_in[17];
    const float* lnw   = (const float*)d_in[18];
    const float* lnb   = (const float*)d_in[19];
    float* out = (float*)d_out;

    float *p_xx, *p_xmix, *p_xxx, *p_xw, *p_xk, *p_xv, *p_xr, *p_xg;
    float *p_r, *p_k, *p_v, *p_gate, *p_w, *p_t1, *p_rw, *p_att, *p_yn;
    float *p_wkvc, *p_states, *p_expws;
    cudaGetSymbolAddress((void**)&p_xx,    g_xx);
    cudaGetSymbolAddress((void**)&p_xmix,  g_xmix);
    cudaGetSymbolAddress((void**)&p_xxx,   g_xxx);
    cudaGetSymbolAddress((void**)&p_xw,    g_xw);
    cudaGetSymbolAddress((void**)&p_xk,    g_xk);
    cudaGetSymbolAddress((void**)&p_xv,    g_xv);
    cudaGetSymbolAddress((void**)&p_xr,    g_xr);
    cudaGetSymbolAddress((void**)&p_xg,    g_xg);
    cudaGetSymbolAddress((void**)&p_r,     g_r);
    cudaGetSymbolAddress((void**)&p_k,     g_k);
    cudaGetSymbolAddress((void**)&p_v,     g_v);
    cudaGetSymbolAddress((void**)&p_gate,  g_gate);
    cudaGetSymbolAddress((void**)&p_w,     g_w);
    cudaGetSymbolAddress((void**)&p_t1,    g_t1);
    cudaGetSymbolAddress((void**)&p_rw,    g_rw);
    cudaGetSymbolAddress((void**)&p_att,   g_att);
    cudaGetSymbolAddress((void**)&p_yn,    g_yn);
    cudaGetSymbolAddress((void**)&p_wkvc,  g_wkvc);
    cudaGetSymbolAddress((void**)&p_states,g_states);
    cudaGetSymbolAddress((void**)&p_expws, g_expws);

    // 1. token shift + mix input
    prep_kernel<<<(BT * DD) / 256, 256>>>(x, tmx, p_xx, p_xmix);
    // 2. xxx = tanh(xmix @ W1)   (8192 x 160 x 1024)
    gemm64<1><<<dim3(3, 128), 256>>>(p_xmix, w1, p_xxx, BT, 160, DD, nullptr);
    // 3. five branch inputs
    branch_mix<<<dim3(BT / 16, 4), 256>>>(x, p_xx, p_xxx, w2,
                                          tmw, tmk, tmv, tmr, tmg,
                                          p_xw, p_xk, p_xv, p_xr, p_xg);
    // 4. projections
    gemm64<0><<<dim3(16, 128), 256>>>(p_xr, Wr, p_r,    BT, DD, DD, nullptr);
    gemm64<0><<<dim3(16, 128), 256>>>(p_xk, Wk, p_k,    BT, DD, DD, nullptr);
    gemm64<0><<<dim3(16, 128), 256>>>(p_xv, Wv, p_v,    BT, DD, DD, nullptr);
    gemm64<2><<<dim3(16, 128), 256>>>(p_xg, Wg, p_gate, BT, DD, DD, nullptr);
    // 5. decay: w = -exp(time_decay + tanh(xw@dw1)@dw2)
    gemm64<1><<<dim3(1, 128),  256>>>(p_xw, dw1, p_t1, BT, 64, DD, nullptr);
    gemm64<3><<<dim3(16, 128), 256>>>(p_t1, dw2, p_w,  BT, DD, 64, tdec);
    // 6. WKV
    wkv_chunk<<<NBH * NCH, 256>>>(p_r, p_k, p_v, p_w, faaaa,
                                  p_rw, p_att, p_wkvc, p_expws);
    wkv_scan<<<NBH, 1024>>>(p_wkvc, p_expws, p_states);
    wkv_state_out<<<NBH * NCH, 256>>>(p_rw, p_states, p_att);
    // 7. group-norm + gate, then output projection
    gnorm_gate<<<BT, 256>>>(p_att, p_gate, lnw, lnb, p_yn);
    gemm64<0><<<dim3(16, 128), 256>>>(p_yn, Wo, out, BT, DD, DD, nullptr);
}

// round 4
// speedup vs baseline: 2.3675x; 2.3675x over previous
#include <cuda_runtime.h>
#include <cuda_bf16.h>
#include <cstdint>
#include <math.h>

#define BB 4
#define TT 2048
#define DD 1024
#define HH 16
#define KK 64
#define BT (BB*TT)          /* 8192 tokens */
#define SCH 32              /* chunk length (numerically safe in fp32) */
#define NCH (TT/SCH)        /* 64 chunks per sequence */
#define NBH (BB*HH)         /* 64 (batch,head) pairs */
#define LOGMIN (-5.2983174f) /* log(0.005) */
#define LN_EPS 6.4e-4f       /* 1e-5 * 8^2 */

// ---------------- scratch (static device arrays; no runtime allocation) ----
static __device__ float g_xx   [BT*DD];
static __device__ float g_xmix [BT*DD];
static __device__ float g_xxx  [BT*160];
static __device__ float g_xw   [BT*DD];
static __device__ float g_xk   [BT*DD];
static __device__ float g_xv   [BT*DD];
static __device__ float g_xr   [BT*DD];
static __device__ float g_xg   [BT*DD];
static __device__ float g_r    [BT*DD];
static __device__ float g_k    [BT*DD];
static __device__ float g_v    [BT*DD];
static __device__ float g_gate [BT*DD];
static __device__ float g_w    [BT*DD];
static __device__ float g_t1   [BT*64];
static __device__ float g_rw   [BT*DD];
static __device__ float g_att  [BT*DD];
static __device__ float g_yn   [BT*DD];
static __device__ float g_wkvc [NBH*NCH*KK*KK];
static __device__ float g_states[NBH*NCH*KK*KK];
static __device__ float g_expws[NBH*NCH*KK];

// ---------------- kernel 1: token shift + mix input ------------------------
__global__ void prep_kernel(const float* __restrict__ x, const float* __restrict__ tmx,
                            float* __restrict__ xx, float* __restrict__ xmix)
{
    size_t idx = (size_t)blockIdx.x * 256 + threadIdx.x;
    int d = (int)(idx & (DD - 1));
    int t = (int)((idx >> 10) & (TT - 1));   // DD = 2^10
    float xv = x[idx];
    float prev = (t == 0) ? 0.f : x[idx - DD];
    float xxv = prev - xv;
    xx[idx] = xxv;
    xmix[idx] = xv + xxv * tmx[d];
}

// ---------------- tf32 tensor-core GEMM ------------------------------------
// C[M,N] = A[M,K] @ B[K,N].  EPI: 0 none, 1 tanh, 2 silu, 3 -exp(bias[n]+v)
// 128x128 CTA tile, BK=16, 8 warps (2x4), warp tile 64x32, mma.m16n8k8.tf32.

__device__ __forceinline__ uint32_t cvt_tf32(float x) {
    uint32_t r;
    asm("cvt.rna.tf32.f32 %0, %1;" : "=r"(r) : "f"(x));
    return r;
}

__device__ __forceinline__ void cp16(void* smem_dst, const void* gmem_src, bool pred) {
    uint32_t saddr = (uint32_t)__cvta_generic_to_shared(smem_dst);
    if (pred)
        asm volatile("cp.async.cg.shared.global [%0], [%1], 16;\n"
                     :: "r"(saddr), "l"(gmem_src));
    else
        asm volatile("cp.async.cg.shared.global [%0], [%1], 16, 0;\n"
                     :: "r"(saddr), "l"(gmem_src));
}

template<int EPI>
__global__ __launch_bounds__(256) void gemm_tf32(
    const float* __restrict__ A, const float* __restrict__ B,
    float* __restrict__ C, int M, int N, int Kd, const float* __restrict__ bias)
{
    __shared__ float As[2][128][20];   // [m][k] pad->stride 20: conflict-free frags
    __shared__ float Bs[2][16][136];   // [k][n] pad->stride 136: conflict-free frags

    const int tid  = threadIdx.x;
    const int lane = tid & 31;
    const int wid  = tid >> 5;
    const int wm   = wid >> 2;          // 0..1
    const int wn   = wid & 3;           // 0..3
    const int m0   = blockIdx.y << 7;
    const int n0   = blockIdx.x << 7;

    float acc[4][4][4];
#pragma unroll
    for (int i = 0; i < 4; i++)
#pragma unroll
        for (int j = 0; j < 4; j++)
#pragma unroll
            for (int r = 0; r < 4; r++) acc[i][j][r] = 0.f;

    const int arow = tid >> 2;          // 0..63
    const int acol = (tid & 3) << 2;    // 0,4,8,12
    const int brow = tid >> 5;          // 0..7
    const int bcol = (tid & 31) << 2;   // 0..124
    const bool bpred = (n0 + bcol) < N;

    auto load_chunk = [&](int k0, int buf) {
#pragma unroll
        for (int r = 0; r < 2; r++) {
            int mr = arow + (r << 6);
            cp16(&As[buf][mr][acol], A + (size_t)(m0 + mr) * Kd + k0 + acol, true);
        }
#pragma unroll
        for (int r = 0; r < 2; r++) {
            int kr = brow + (r << 3);
            cp16(&Bs[buf][kr][bcol], B + (size_t)(k0 + kr) * N + n0 + bcol, bpred);
        }
        asm volatile("cp.async.commit_group;\n");
    };

    auto compute = [&](int buf) {
#pragma unroll
        for (int ks = 0; ks < 2; ks++) {
            const int kb   = (ks << 3) + (lane & 3);
            const int mrow = (wm << 6) + (lane >> 2);
            const int ncol = (wn << 5) + (lane >> 2);
            uint32_t af[4][4], bf[4][2];
#pragma unroll
            for (int mi = 0; mi < 4; mi++) {
                af[mi][0] = cvt_tf32(As[buf][mrow + mi*16    ][kb    ]);
                af[mi][1] = cvt_tf32(As[buf][mrow + mi*16 + 8][kb    ]);
                af[mi][2] = cvt_tf32(As[buf][mrow + mi*16    ][kb + 4]);
                af[mi][3] = cvt_tf32(As[buf][mrow + mi*16 + 8][kb + 4]);
            }
#pragma unroll
            for (int ni = 0; ni < 4; ni++) {
                bf[ni][0] = cvt_tf32(Bs[buf][(ks<<3) + (lane&3)    ][ncol + ni*8]);
                bf[ni][1] = cvt_tf32(Bs[buf][(ks<<3) + (lane&3) + 4][ncol + ni*8]);
            }
#pragma unroll
            for (int mi = 0; mi < 4; mi++)
#pragma unroll
                for (int ni = 0; ni < 4; ni++)
                    asm volatile(
                        "mma.sync.aligned.m16n8k8.row.col.f32.tf32.tf32.f32 "
                        "{%0,%1,%2,%3}, {%4,%5,%6,%7}, {%8,%9}, {%0,%1,%2,%3};\n"
                        : "+f"(acc[mi][ni][0]), "+f"(acc[mi][ni][1]),
                          "+f"(acc[mi][ni][2]), "+f"(acc[mi][ni][3])
                        : "r"(af[mi][0]), "r"(af[mi][1]), "r"(af[mi][2]), "r"(af[mi][3]),
                          "r"(bf[ni][0]), "r"(bf[ni][1]));
        }
    };

    load_chunk(0, 0);
    asm volatile("cp.async.wait_group 0;\n");
    __syncthreads();

    const int nK = Kd >> 4;
    for (int kc = 0; kc < nK; kc++) {
        int buf = kc & 1;
        if (kc + 1 < nK) load_chunk((kc + 1) << 4, buf ^ 1);
        else asm volatile("cp.async.commit_group;\n");
        compute(buf);
        asm volatile("cp.async.wait_group 0;\n");
        __syncthreads();
    }

    // epilogue
#pragma unroll
    for (int mi = 0; mi < 4; mi++) {
        int m = m0 + (wm << 6) + mi*16 + (lane >> 2);
#pragma unroll
        for (int ni = 0; ni < 4; ni++) {
            int n = n0 + (wn << 5) + ni*8 + ((lane & 3) << 1);
#pragma unroll
            for (int rr = 0; rr < 4; rr++) {
                int mm = m + ((rr >> 1) << 3);
                int nn = n + (rr & 1);
                if (nn < N) {
                    float val = acc[mi][ni][rr];
                    if (EPI == 1) val = tanhf(val);
                    else if (EPI == 2) val = val * (1.f / (1.f + expf(-val)));
                    else if (EPI == 3) val = -expf(bias[nn] + val);
                    C[(size_t)mm * N + nn] = val;
                }
            }
        }
    }
}

// ---------------- kernel 3: 5-branch LoRA mix -------------------------------
__global__ __launch_bounds__(256) void branch_mix(
    const float* __restrict__ x, const float* __restrict__ xx,
    const float* __restrict__ xxx, const float* __restrict__ W2,
    const float* __restrict__ tmw, const float* __restrict__ tmk,
    const float* __restrict__ tmv, const float* __restrict__ tmr,
    const float* __restrict__ tmg,
    float* __restrict__ xw, float* __restrict__ xk, float* __restrict__ xv,
    float* __restrict__ xr, float* __restrict__ xg)
{
    __shared__ float sx[16][160];
    int tid = threadIdx.x;
    int t0 = blockIdx.x * 16;
    int d  = blockIdx.y * 256 + tid;
    for (int e = tid; e < 16 * 160; e += 256) {
        int tok = e / 160, c = e - tok * 160;
        sx[tok][c] = xxx[(size_t)(t0 + tok) * 160 + c];
    }
    __syncthreads();
    float m[5][16];
#pragma unroll
    for (int f = 0; f < 5; f++)
#pragma unroll
        for (int tok = 0; tok < 16; tok++) m[f][tok] = 0.f;
    for (int f = 0; f < 5; f++) {
        for (int i = 0; i < 32; i++) {
            float wv = W2[(size_t)(f * 32 + i) * DD + d];
#pragma unroll
            for (int tok = 0; tok < 16; tok++) m[f][tok] += sx[tok][f * 32 + i] * wv;
        }
    }
    float t_w = tmw[d], t_k = tmk[d], t_v = tmv[d], t_r = tmr[d], t_g = tmg[d];
    for (int tok = 0; tok < 16; tok++) {
        size_t gi = (size_t)(t0 + tok) * DD + d;
        float xv_ = x[gi], xxv = xx[gi];
        xw[gi] = xv_ + xxv * (t_w + m[0][tok]);
        xk[gi] = xv_ + xxv * (t_k + m[1][tok]);
        xv[gi] = xv_ + xxv * (t_v + m[2][tok]);
        xr[gi] = xv_ + xxv * (t_r + m[3][tok]);
        xg[gi] = xv_ + xxv * (t_g + m[4][tok]);
    }
}

// ---------------- WKV pass 1: per-chunk intra work + summaries --------------
__global__ __launch_bounds__(256) void wkv_chunk(
    const float* __restrict__ r, const float* __restrict__ k,
    const float* __restrict__ v, const float* __restrict__ w,
    const float* __restrict__ u,
    float* __restrict__ rw, float* __restrict__ att,
    float* __restrict__ wkvc, float* __restrict__ expws)
{
    __shared__ float sr [SCH][KK + 1];
    __shared__ float sk [SCH][KK + 1];
    __shared__ float sv [SCH][KK + 1];
    __shared__ float swl[SCH][KK + 1];   // wlog, later overwritten with kw
    __shared__ float swc[SCH][KK + 1];   // inclusive cumsum; later reused for A
    __shared__ float soff[KK];
    __shared__ float sdiag[SCH];
    float* sA = &swc[0][0];              // 1024 floats inside swc region

    int tid = threadIdx.x;
    int bid = blockIdx.x;
    int n = bid & (NCH - 1);
    int h = (bid / NCH) & (HH - 1);
    int b = bid / (NCH * HH);
    size_t base = ((size_t)(b * TT + n * SCH)) * DD + h * KK;

    for (int e = tid; e < SCH * KK; e += 256) {
        int t = e >> 6, c = e & 63;
        size_t gi = base + (size_t)t * DD + c;
        sr [t][c] = r[gi];
        sk [t][c] = k[gi];
        sv [t][c] = v[gi];
        swl[t][c] = fmaxf(w[gi], LOGMIN);
    }
    __syncthreads();
    if (tid < KK) {
        float c = 0.f;
        for (int t = 0; t < SCH; t++) { c += swl[t][tid]; swc[t][tid] = c; }
        expws[(size_t)bid * KK + tid] = expf(c);
        soff[tid] = swc[16][tid] - swl[16][tid];   // shifted at chunk center
    }
    __syncthreads();
    if (tid < SCH) {   // diagonal term: sum_k r*u*k
        float acc = 0.f;
        for (int c = 0; c < KK; c++) acc += sr[tid][c] * u[h * KK + c] * sk[tid][c];
        sdiag[tid] = acc;
    }
    __syncthreads();
    // elementwise transforms (overwrite sr->r_decay, sk->k_inv, swl->kw); emit rw
    for (int e = tid; e < SCH * KK; e += 256) {
        int t = e >> 6, c = e & 63;
        float wl = swl[t][c], wc = swc[t][c];
        float shft = wc - wl;                 // exclusive cumsum
        float off  = soff[c];
        float ws   = swc[SCH - 1][c];
        float rv = sr[t][c], kv = sk[t][c];
        rw[base + (size_t)t * DD + c] = rv * expf(shft);       // r * w_intra
        sr [t][c] = rv * expf(shft - off);                     // r_decay
        sk [t][c] = kv * expf(off - wc);                       // k_inv
        swl[t][c] = kv * expf(ws - wc);                        // k * w_inter
    }
    __syncthreads();
    // A = tril(r_decay @ k_inv^T, -1) + diag  (32x32) — goes into swc region
    for (int e = tid; e < SCH * SCH; e += 256) {
        int i = e >> 5, j = e & 31;
        float acc = 0.f;
        if (i > j) {
            for (int c = 0; c < KK; c++) acc += sr[i][c] * sk[j][c];
        } else if (i == j) acc = sdiag[i];
        sA[e] = acc;
    }
    __syncthreads();
    // intra-chunk output: out = A @ v
    for (int e = tid; e < SCH * KK; e += 256) {
        int t = e >> 6, vv = e & 63;
        float acc = 0.f;
        for (int j = 0; j <= t; j++) acc += sA[t * SCH + j] * sv[j][vv];
        att[base + (size_t)t * DD + vv] = acc;
    }
    // chunk summary: wkv_c[k][v] = sum_t kw[t][k]*v[t][v]
    for (int e = tid; e < KK * KK; e += 256) {
        int c = e >> 6, vv = e & 63;
        float acc = 0.f;
        for (int t = 0; t < SCH; t++) acc += swl[t][c] * sv[t][vv];
        wkvc[(size_t)bid * (KK * KK) + e] = acc;
    }
}

// ---------------- WKV pass 2: serial scan over chunks -----------------------
__global__ __launch_bounds__(1024) void wkv_scan(
    const float* __restrict__ wkvc, const float* __restrict__ expws,
    float* __restrict__ states)
{
    int bh = blockIdx.x;
    int tid = threadIdx.x;
    int c  = tid >> 4;
    int v0 = (tid & 15) << 2;
    float s0 = 0.f, s1 = 0.f, s2 = 0.f, s3 = 0.f;
    size_t eb = (size_t)bh * NCH * KK;
    size_t sb = (size_t)bh * NCH * KK * KK + (size_t)c * KK + v0;
    for (int n = 0; n < NCH; n++) {
        float wd = expws[eb + (size_t)n * KK + c];
        size_t o = sb + (size_t)n * KK * KK;
        float4 st; st.x = s0; st.y = s1; st.z = s2; st.w = s3;
        *(float4*)(states + o) = st;                // state BEFORE chunk n
        float4 wc4 = *(const float4*)(wkvc + o);
        s0 = s0 * wd + wc4.x; s1 = s1 * wd + wc4.y;
        s2 = s2 * wd + wc4.z; s3 = s3 * wd + wc4.w;
    }
}

// ---------------- WKV pass 3: apply carried state ---------------------------
__global__ __launch_bounds__(256) void wkv_state_out(
    const float* __restrict__ rw, const float* __restrict__ states,
    float* __restrict__ att)
{
    __shared__ float sst[KK][KK];
    __shared__ float srw[SCH][KK];
    int tid = threadIdx.x, bid = blockIdx.x;
    int n = bid & (NCH - 1);
    int h = (bid / NCH) & (HH - 1);
    int b = bid / (NCH * HH);
    size_t base = ((size_t)(b * TT + n * SCH)) * DD + h * KK;
    size_t stb = (size_t)bid * (KK * KK);
    for (int e = tid; e < KK * KK; e += 256) sst[e >> 6][e & 63] = states[stb + e];
    for (int e = tid; e < SCH * KK; e += 256) {
        int t = e >> 6, c = e & 63;
        srw[t][c] = rw[base + (size_t)t * DD + c];
    }
    __syncthreads();
    for (int e = tid; e < SCH * KK; e += 256) {
        int t = e >> 6, vv = e & 63;
        float acc = 0.f;
#pragma unroll 8
        for (int c = 0; c < KK; c++) acc += srw[t][c] * sst[c][vv];
        size_t gi = base + (size_t)t * DD + vv;
        att[gi] += acc;
    }
}

// ---------------- group-norm (per head) + gate ------------------------------
__global__ __launch_bounds__(256) void gnorm_gate(
    const float* __restrict__ att, const float* __restrict__ gate,
    const float* __restrict__ lnw, const float* __restrict__ lnb,
    float* __restrict__ y)
{
    int token = blockIdx.x, tid = threadIdx.x;
    size_t base = (size_t)token * DD + tid * 4;
    float4 v4 = *(const float4*)(att + base);
    float s  = v4.x + v4.y + v4.z + v4.w;
    float ss = v4.x * v4.x + v4.y * v4.y + v4.z * v4.z + v4.w * v4.w;
#pragma unroll
    for (int o = 1; o < 16; o <<= 1) {
        s  += __shfl_xor_sync(0xffffffffu, s,  o);
        ss += __shfl_xor_sync(0xffffffffu, ss, o);
    }
    float mean = s * (1.f / KK);
    float var  = ss * (1.f / KK) - mean * mean;
    float rstd = rsqrtf(var + LN_EPS);
    float4 g4 = *(const float4*)(gate + base);
    float4 w4 = *(const float4*)(lnw + tid * 4);
    float4 b4 = *(const float4*)(lnb + tid * 4);
    float4 o4;
    o4.x = ((v4.x - mean) * rstd * w4.x + b4.x) * g4.x;
    o4.y = ((v4.y - mean) * rstd * w4.y + b4.y) * g4.y;
    o4.z = ((v4.z - mean) * rstd * w4.z + b4.z) * g4.z;
    o4.w = ((v4.w - mean) * rstd * w4.w + b4.w) * g4.w;
    *(float4*)(y + base) = o4;
}

// ---------------- launch ----------------------------------------------------
extern "C" void kernel_launch(void* const* d_in, const int* in_sizes, int n_in,
                              void* d_out, int out_size)
{
    const float* x     = (const float*)d_in[0];
    const float* tmx   = (const float*)d_in[1];
    const float* tmw   = (const float*)d_in[2];
    const float* tmk   = (const float*)d_in[3];
    const float* tmv   = (const float*)d_in[4];
    const float* tmr   = (const float*)d_in[5];
    const float* tmg   = (const float*)d_in[6];
    const float* w1    = (const float*)d_in[7];
    const float* w2    = (const float*)d_in[8];
    const float* tdec  = (const float*)d_in[9];
    const float* dw1   = (const float*)d_in[10];
    const float* dw2   = (const float*)d_in[11];
    const float* faaaa = (const float*)d_in[12];
    const float* Wr    = (const float*)d_in[13];
    const float* Wk    = (const float*)d_in[14];
    const float* Wv    = (const float*)d_in[15];
    const float* Wg    = (const float*)d_in[16];
    const float* Wo    = (const float*)d_in[17];
    const float* lnw   = (const float*)d_in[18];
    const float* lnb   = (const float*)d_in[19];
    float* out = (float*)d_out;

    float *p_xx, *p_xmix, *p_xxx, *p_xw, *p_xk, *p_xv, *p_xr, *p_xg;
    float *p_r, *p_k, *p_v, *p_gate, *p_w, *p_t1, *p_rw, *p_att, *p_yn;
    float *p_wkvc, *p_states, *p_expws;
    cudaGetSymbolAddress((void**)&p_xx,    g_xx);
    cudaGetSymbolAddress((void**)&p_xmix,  g_xmix);
    cudaGetSymbolAddress((void**)&p_xxx,   g_xxx);
    cudaGetSymbolAddress((void**)&p_xw,    g_xw);
    cudaGetSymbolAddress((void**)&p_xk,    g_xk);
    cudaGetSymbolAddress((void**)&p_xv,    g_xv);
    cudaGetSymbolAddress((void**)&p_xr,    g_xr);
    cudaGetSymbolAddress((void**)&p_xg,    g_xg);
    cudaGetSymbolAddress((void**)&p_r,     g_r);
    cudaGetSymbolAddress((void**)&p_k,     g_k);
    cudaGetSymbolAddress((void**)&p_v,     g_v);
    cudaGetSymbolAddress((void**)&p_gate,  g_gate);
    cudaGetSymbolAddress((void**)&p_w,     g_w);
    cudaGetSymbolAddress((void**)&p_t1,    g_t1);
    cudaGetSymbolAddress((void**)&p_rw,    g_rw);
    cudaGetSymbolAddress((void**)&p_att,   g_att);
    cudaGetSymbolAddress((void**)&p_yn,    g_yn);
    cudaGetSymbolAddress((void**)&p_wkvc,  g_wkvc);
    cudaGetSymbolAddress((void**)&p_states,g_states);
    cudaGetSymbolAddress((void**)&p_expws, g_expws);

    // 1. token shift + mix input
    prep_kernel<<<(BT * DD) / 256, 256>>>(x, tmx, p_xx, p_xmix);
    // 2. xxx = tanh(xmix @ W1)   (8192 x 160 x 1024)
    gemm_tf32<1><<<dim3(2, 64), 256>>>(p_xmix, w1, p_xxx, BT, 160, DD, nullptr);
    // 3. five branch inputs
    branch_mix<<<dim3(BT / 16, 4), 256>>>(x, p_xx, p_xxx, w2,
                                          tmw, tmk, tmv, tmr, tmg,
                                          p_xw, p_xk, p_xv, p_xr, p_xg);
    // 4. projections (tf32 tensor cores)
    gemm_tf32<0><<<dim3(8, 64), 256>>>(p_xr, Wr, p_r,    BT, DD, DD, nullptr);
    gemm_tf32<0><<<dim3(8, 64), 256>>>(p_xk, Wk, p_k,    BT, DD, DD, nullptr);
    gemm_tf32<0><<<dim3(8, 64), 256>>>(p_xv, Wv, p_v,    BT, DD, DD, nullptr);
    gemm_tf32<2><<<dim3(8, 64), 256>>>(p_xg, Wg, p_gate, BT, DD, DD, nullptr);
    // 5. decay: w = -exp(time_decay + tanh(xw@dw1)@dw2)
    gemm_tf32<1><<<dim3(1, 64), 256>>>(p_xw, dw1, p_t1, BT, 64, DD, nullptr);
    gemm_tf32<3><<<dim3(8, 64), 256>>>(p_t1, dw2, p_w,  BT, DD, 64, tdec);
    // 6. WKV
    wkv_chunk<<<NBH * NCH, 256>>>(p_r, p_k, p_v, p_w, faaaa,
                                  p_rw, p_att, p_wkvc, p_expws);
    wkv_scan<<<NBH, 1024>>>(p_wkvc, p_expws, p_states);
    wkv_state_out<<<NBH * NCH, 256>>>(p_rw, p_states, p_att);
    // 7. group-norm + gate, then output projection
    gnorm_gate<<<BT, 256>>>(p_att, p_gate, lnw, lnb, p_yn);
    gemm_tf32<0><<<dim3(8, 64), 256>>>(p_yn, Wo, out, BT, DD, DD, nullptr);
}

// round 5
// speedup vs baseline: 2.8981x; 1.2241x over previous
#include <cuda_runtime.h>
#include <cuda_bf16.h>
#include <cstdint>
#include <math.h>

#define BB 4
#define TT 2048
#define DD 1024
#define HH 16
#define KK 64
#define BT (BB*TT)          /* 8192 tokens */
#define SCH 32              /* chunk length (numerically safe in fp32) */
#define NCH (TT/SCH)        /* 64 chunks per sequence */
#define NBH (BB*HH)         /* 64 (batch,head) pairs */
#define LOGMIN (-5.2983174f) /* log(0.005) */
#define LN_EPS 6.4e-4f       /* 1e-5 * 8^2 */

// ---------------- scratch (static device arrays; no runtime allocation) ----
static __device__ float g_xx   [BT*DD];
static __device__ float g_xmix [BT*DD];
static __device__ float g_xxx  [BT*160];
static __device__ float g_xw   [BT*DD];
static __device__ float g_xk   [BT*DD];
static __device__ float g_xv   [BT*DD];
static __device__ float g_xr   [BT*DD];
static __device__ float g_xg   [BT*DD];
static __device__ float g_r    [BT*DD];
static __device__ float g_k    [BT*DD];
static __device__ float g_v    [BT*DD];
static __device__ float g_gate [BT*DD];
static __device__ float g_w    [BT*DD];
static __device__ float g_t1   [BT*64];
static __device__ float g_rw   [BT*DD];
static __device__ float g_att  [BT*DD];
static __device__ float g_yn   [BT*DD];
static __device__ float g_wkvc [NBH*NCH*KK*KK];
static __device__ float g_states[NBH*NCH*KK*KK];
static __device__ float g_expws[NBH*NCH*KK];

// ---------------- kernel 1: token shift + mix input ------------------------
__global__ void prep_kernel(const float* __restrict__ x, const float* __restrict__ tmx,
                            float* __restrict__ xx, float* __restrict__ xmix)
{
    size_t idx = (size_t)blockIdx.x * 256 + threadIdx.x;
    int d = (int)(idx & (DD - 1));
    int t = (int)((idx >> 10) & (TT - 1));   // DD = 2^10
    float xv = x[idx];
    float prev = (t == 0) ? 0.f : x[idx - DD];
    float xxv = prev - xv;
    xx[idx] = xxv;
    xmix[idx] = xv + xxv * tmx[d];
}

// ---------------- tf32 tensor-core GEMM ------------------------------------
__device__ __forceinline__ uint32_t cvt_tf32(float x) {
    uint32_t r;
    asm("cvt.rna.tf32.f32 %0, %1;" : "=r"(r) : "f"(x));
    return r;
}

__device__ __forceinline__ void cp16(void* smem_dst, const void* gmem_src, bool pred) {
    uint32_t saddr = (uint32_t)__cvta_generic_to_shared(smem_dst);
    if (pred)
        asm volatile("cp.async.cg.shared.global [%0], [%1], 16;\n"
                     :: "r"(saddr), "l"(gmem_src));
    else
        asm volatile("cp.async.cg.shared.global [%0], [%1], 16, 0;\n"
                     :: "r"(saddr), "l"(gmem_src));
}

// shared GEMM body: 128x128 CTA tile, BK=16, 8 warps (2x4), warp tile 64x32
// epi: 0 none, 1 tanh, 2 silu, 3 -exp(bias[n]+v)
__device__ __forceinline__ void gemm_body(
    const float* __restrict__ A, const float* __restrict__ B,
    float* __restrict__ C, int N, int Kd, const float* __restrict__ bias,
    int epi, int m0, int n0,
    float (*As)[128][20], float (*Bs)[16][136])
{
    const int tid  = threadIdx.x;
    const int lane = tid & 31;
    const int wid  = tid >> 5;
    const int wm   = wid >> 2;
    const int wn   = wid & 3;

    float acc[4][4][4];
#pragma unroll
    for (int i = 0; i < 4; i++)
#pragma unroll
        for (int j = 0; j < 4; j++)
#pragma unroll
            for (int r = 0; r < 4; r++) acc[i][j][r] = 0.f;

    const int arow = tid >> 2;
    const int acol = (tid & 3) << 2;
    const int brow = tid >> 5;
    const int bcol = (tid & 31) << 2;
    const bool bpred = (n0 + bcol) < N;

    auto load_chunk = [&](int k0, int buf) {
#pragma unroll
        for (int r = 0; r < 2; r++) {
            int mr = arow + (r << 6);
            cp16(&As[buf][mr][acol], A + (size_t)(m0 + mr) * Kd + k0 + acol, true);
        }
#pragma unroll
        for (int r = 0; r < 2; r++) {
            int kr = brow + (r << 3);
            cp16(&Bs[buf][kr][bcol], B + (size_t)(k0 + kr) * N + n0 + bcol, bpred);
        }
        asm volatile("cp.async.commit_group;\n");
    };

    auto compute = [&](int buf) {
#pragma unroll
        for (int ks = 0; ks < 2; ks++) {
            const int kb   = (ks << 3) + (lane & 3);
            const int mrow = (wm << 6) + (lane >> 2);
            const int ncol = (wn << 5) + (lane >> 2);
            uint32_t af[4][4], bf[4][2];
#pragma unroll
            for (int mi = 0; mi < 4; mi++) {
                af[mi][0] = cvt_tf32(As[buf][mrow + mi*16    ][kb    ]);
                af[mi][1] = cvt_tf32(As[buf][mrow + mi*16 + 8][kb    ]);
                af[mi][2] = cvt_tf32(As[buf][mrow + mi*16    ][kb + 4]);
                af[mi][3] = cvt_tf32(As[buf][mrow + mi*16 + 8][kb + 4]);
            }
#pragma unroll
            for (int ni = 0; ni < 4; ni++) {
                bf[ni][0] = cvt_tf32(Bs[buf][(ks<<3) + (lane&3)    ][ncol + ni*8]);
                bf[ni][1] = cvt_tf32(Bs[buf][(ks<<3) + (lane&3) + 4][ncol + ni*8]);
            }
#pragma unroll
            for (int mi = 0; mi < 4; mi++)
#pragma unroll
                for (int ni = 0; ni < 4; ni++)
                    asm volatile(
                        "mma.sync.aligned.m16n8k8.row.col.f32.tf32.tf32.f32 "
                        "{%0,%1,%2,%3}, {%4,%5,%6,%7}, {%8,%9}, {%0,%1,%2,%3};\n"
                        : "+f"(acc[mi][ni][0]), "+f"(acc[mi][ni][1]),
                          "+f"(acc[mi][ni][2]), "+f"(acc[mi][ni][3])
                        : "r"(af[mi][0]), "r"(af[mi][1]), "r"(af[mi][2]), "r"(af[mi][3]),
                          "r"(bf[ni][0]), "r"(bf[ni][1]));
        }
    };

    load_chunk(0, 0);
    asm volatile("cp.async.wait_group 0;\n");
    __syncthreads();

    const int nK = Kd >> 4;
    for (int kc = 0; kc < nK; kc++) {
        int buf = kc & 1;
        if (kc + 1 < nK) load_chunk((kc + 1) << 4, buf ^ 1);
        else asm volatile("cp.async.commit_group;\n");
        compute(buf);
        asm volatile("cp.async.wait_group 0;\n");
        __syncthreads();
    }

#pragma unroll
    for (int mi = 0; mi < 4; mi++) {
        int m = m0 + (wm << 6) + mi*16 + (lane >> 2);
#pragma unroll
        for (int ni = 0; ni < 4; ni++) {
            int n = n0 + (wn << 5) + ni*8 + ((lane & 3) << 1);
#pragma unroll
            for (int rr = 0; rr < 4; rr++) {
                int mm = m + ((rr >> 1) << 3);
                int nn = n + (rr & 1);
                if (nn < N) {
                    float val = acc[mi][ni][rr];
                    if (epi == 1) val = tanhf(val);
                    else if (epi == 2) val = val * (1.f / (1.f + expf(-val)));
                    else if (epi == 3) val = -expf(bias[nn] + val);
                    C[(size_t)mm * N + nn] = val;
                }
            }
        }
    }
}

template<int EPI>
__global__ __launch_bounds__(256) void gemm_tf32(
    const float* __restrict__ A, const float* __restrict__ B,
    float* __restrict__ C, int M, int N, int Kd, const float* __restrict__ bias)
{
    __shared__ float As[2][128][20];
    __shared__ float Bs[2][16][136];
    int n0 = blockIdx.x << 7;
    if (n0 >= N) return;
    gemm_body(A, B, C, N, Kd, bias, EPI, blockIdx.y << 7, n0, As, Bs);
}

// batched variant: z selects one of 5 independent GEMMs (all Kd=1024)
struct BatchArgs {
    const float* A[5];
    const float* B[5];
    float*       C[5];
    int          N[5];
    int          epi[5];
};

__global__ __launch_bounds__(256) void gemm_tf32_batch(BatchArgs args)
{
    __shared__ float As[2][128][20];
    __shared__ float Bs[2][16][136];
    int z = blockIdx.z;
    int N = args.N[z];
    int n0 = blockIdx.x << 7;
    if (n0 >= N) return;
    gemm_body(args.A[z], args.B[z], args.C[z], N, DD, nullptr,
              args.epi[z], blockIdx.y << 7, n0, As, Bs);
}

// ---------------- kernel 3: 5-branch LoRA mix -------------------------------
__global__ __launch_bounds__(256) void branch_mix(
    const float* __restrict__ x, const float* __restrict__ xx,
    const float* __restrict__ xxx, const float* __restrict__ W2,
    const float* __restrict__ tmw, const float* __restrict__ tmk,
    const float* __restrict__ tmv, const float* __restrict__ tmr,
    const float* __restrict__ tmg,
    float* __restrict__ xw, float* __restrict__ xk, float* __restrict__ xv,
    float* __restrict__ xr, float* __restrict__ xg)
{
    __shared__ float sx[16][160];
    int tid = threadIdx.x;
    int t0 = blockIdx.x * 16;
    int d  = blockIdx.y * 256 + tid;
    for (int e = tid; e < 16 * 160; e += 256) {
        int tok = e / 160, c = e - tok * 160;
        sx[tok][c] = xxx[(size_t)(t0 + tok) * 160 + c];
    }
    __syncthreads();
    float m[5][16];
#pragma unroll
    for (int f = 0; f < 5; f++)
#pragma unroll
        for (int tok = 0; tok < 16; tok++) m[f][tok] = 0.f;
    for (int f = 0; f < 5; f++) {
        for (int i = 0; i < 32; i++) {
            float wv = W2[(size_t)(f * 32 + i) * DD + d];
#pragma unroll
            for (int tok = 0; tok < 16; tok++) m[f][tok] += sx[tok][f * 32 + i] * wv;
        }
    }
    float t_w = tmw[d], t_k = tmk[d], t_v = tmv[d], t_r = tmr[d], t_g = tmg[d];
    for (int tok = 0; tok < 16; tok++) {
        size_t gi = (size_t)(t0 + tok) * DD + d;
        float xv_ = x[gi], xxv = xx[gi];
        xw[gi] = xv_ + xxv * (t_w + m[0][tok]);
        xk[gi] = xv_ + xxv * (t_k + m[1][tok]);
        xv[gi] = xv_ + xxv * (t_v + m[2][tok]);
        xr[gi] = xv_ + xxv * (t_r + m[3][tok]);
        xg[gi] = xv_ + xxv * (t_g + m[4][tok]);
    }
}

// ---------------- WKV pass 1: per-chunk intra work + summaries --------------
#define PAD 4
__global__ __launch_bounds__(256) void wkv_chunk(
    const float* __restrict__ r, const float* __restrict__ k,
    const float* __restrict__ v, const float* __restrict__ w,
    const float* __restrict__ u,
    float* __restrict__ rw, float* __restrict__ att,
    float* __restrict__ wkvc, float* __restrict__ expws)
{
    __shared__ float sr [SCH][KK + PAD];
    __shared__ float sk [SCH][KK + PAD];
    __shared__ float sv [SCH][KK + PAD];
    __shared__ float swl[SCH][KK + PAD];   // wlog -> kw
    __shared__ float swc[SCH][KK + PAD];   // cumsum; later reused for A
    __shared__ float soff[KK];
    __shared__ float sdiag[SCH];
    float* sA = &swc[0][0];                // 1024 floats inside swc region

    int tid = threadIdx.x;
    int bid = blockIdx.x;
    int n = bid & (NCH - 1);
    int h = (bid / NCH) & (HH - 1);
    int b = bid / (NCH * HH);
    size_t base = ((size_t)(b * TT + n * SCH)) * DD + h * KK;

    for (int e = tid; e < SCH * KK; e += 256) {
        int t = e >> 6, c = e & 63;
        size_t gi = base + (size_t)t * DD + c;
        sr [t][c] = r[gi];
        sk [t][c] = k[gi];
        sv [t][c] = v[gi];
        swl[t][c] = fmaxf(w[gi], LOGMIN);
    }
    __syncthreads();
    if (tid < KK) {
        float c = 0.f;
        for (int t = 0; t < SCH; t++) { c += swl[t][tid]; swc[t][tid] = c; }
        expws[(size_t)bid * KK + tid] = expf(c);
        soff[tid] = swc[16][tid] - swl[16][tid];
    }
    __syncthreads();
    if (tid < SCH) {   // diagonal: sum_k r*u*k
        float acc = 0.f;
        const float4* rp = (const float4*)&sr[tid][0];
        const float4* kp = (const float4*)&sk[tid][0];
        const float4* up = (const float4*)(u + h * KK);
        for (int c = 0; c < 16; c++) {
            float4 a = rp[c], bb = kp[c], uu = up[c];
            acc += a.x*uu.x*bb.x + a.y*uu.y*bb.y + a.z*uu.z*bb.z + a.w*uu.w*bb.w;
        }
        sdiag[tid] = acc;
    }
    __syncthreads();
    // elementwise transforms (overwrite sr->r_decay, sk->k_inv, swl->kw)
    for (int e = tid; e < SCH * KK; e += 256) {
        int t = e >> 6, c = e & 63;
        float wl = swl[t][c], wc = swc[t][c];
        float shft = wc - wl;
        float off  = soff[c];
        float ws   = swc[SCH - 1][c];
        float rv = sr[t][c], kv = sk[t][c];
        rw[base + (size_t)t * DD + c] = rv * expf(shft);       // r * w_intra
        sr [t][c] = rv * expf(shft - off);                     // r_decay
        sk [t][c] = kv * expf(off - wc);                       // k_inv
        swl[t][c] = kv * expf(ws - wc);                        // k * w_inter
    }
    __syncthreads();
    // A = tril(r_decay @ k_inv^T, -1) + diag  (32x32) -> swc region
    for (int e = tid; e < SCH * SCH; e += 256) {
        int i = e >> 5, j = e & 31;
        float acc = 0.f;
        if (i > j) {
            const float4* rp = (const float4*)&sr[i][0];
            const float4* kp = (const float4*)&sk[j][0];
#pragma unroll 4
            for (int c = 0; c < 16; c++) {
                float4 a = rp[c], bb = kp[c];
                acc += a.x*bb.x + a.y*bb.y + a.z*bb.z + a.w*bb.w;
            }
        } else if (i == j) acc = sdiag[i];
        sA[e] = acc;
    }
    __syncthreads();
    // intra-chunk output: out = A @ v   (thread = (t, 4 v-cols))
    for (int item = tid; item < SCH * 16; item += 256) {
        int t = item >> 4, v4 = item & 15;
        float4 acc = {0.f, 0.f, 0.f, 0.f};
        const float* arow = sA + t * SCH;
        for (int j = 0; j <= t; j++) {
            float a = arow[j];
            float4 vv = *(const float4*)&sv[j][v4 << 2];
            acc.x += a * vv.x; acc.y += a * vv.y;
            acc.z += a * vv.z; acc.w += a * vv.w;
        }
        *(float4*)(att + base + (size_t)t * DD + (v4 << 2)) = acc;
    }
    // chunk summary: wkv_c[c][v] = sum_t kw[t][c]*v[t][v]; thread owns 4x4 tile
    {
        int c0 = (tid >> 4) << 2;
        int v0 = (tid & 15) << 2;
        float acc[4][4];
#pragma unroll
        for (int i = 0; i < 4; i++)
#pragma unroll
            for (int j = 0; j < 4; j++) acc[i][j] = 0.f;
        for (int t = 0; t < SCH; t++) {
            float4 kw = *(const float4*)&swl[t][c0];
            float4 vv = *(const float4*)&sv[t][v0];
            float ka[4] = {kw.x, kw.y, kw.z, kw.w};
            float va[4] = {vv.x, vv.y, vv.z, vv.w};
#pragma unroll
            for (int i = 0; i < 4; i++)
#pragma unroll
                for (int j = 0; j < 4; j++) acc[i][j] += ka[i] * va[j];
        }
        size_t ob = (size_t)bid * (KK * KK);
#pragma unroll
        for (int i = 0; i < 4; i++) {
            float4 o4; o4.x = acc[i][0]; o4.y = acc[i][1];
            o4.z = acc[i][2]; o4.w = acc[i][3];
            *(float4*)(wkvc + ob + (size_t)(c0 + i) * KK + v0) = o4;
        }
    }
}

// ---------------- WKV pass 2: serial scan over chunks -----------------------
__global__ __launch_bounds__(1024) void wkv_scan(
    const float* __restrict__ wkvc, const float* __restrict__ expws,
    float* __restrict__ states)
{
    int bh = blockIdx.x;
    int tid = threadIdx.x;
    int c  = tid >> 4;
    int v0 = (tid & 15) << 2;
    float s0 = 0.f, s1 = 0.f, s2 = 0.f, s3 = 0.f;
    size_t eb = (size_t)bh * NCH * KK;
    size_t sb = (size_t)bh * NCH * KK * KK + (size_t)c * KK + v0;
    for (int n = 0; n < NCH; n++) {
        float wd = expws[eb + (size_t)n * KK + c];
        size_t o = sb + (size_t)n * KK * KK;
        float4 st; st.x = s0; st.y = s1; st.z = s2; st.w = s3;
        *(float4*)(states + o) = st;
        float4 wc4 = *(const float4*)(wkvc + o);
        s0 = s0 * wd + wc4.x; s1 = s1 * wd + wc4.y;
        s2 = s2 * wd + wc4.z; s3 = s3 * wd + wc4.w;
    }
}

// ---------------- WKV pass 3: apply carried state ---------------------------
__global__ __launch_bounds__(256) void wkv_state_out(
    const float* __restrict__ rw, const float* __restrict__ states,
    float* __restrict__ att)
{
    __shared__ float sst[KK][KK];
    __shared__ float srw[SCH][KK];
    int tid = threadIdx.x, bid = blockIdx.x;
    int n = bid & (NCH - 1);
    int h = (bid / NCH) & (HH - 1);
    int b = bid / (NCH * HH);
    size_t base = ((size_t)(b * TT + n * SCH)) * DD + h * KK;
    size_t stb = (size_t)bid * (KK * KK);
    for (int e = tid; e < KK * KK / 4; e += 256)
        ((float4*)&sst[0][0])[e] = ((const float4*)(states + stb))[e];
    for (int e = tid; e < SCH * KK / 4; e += 256) {
        int t = e >> 4, c4 = e & 15;
        ((float4*)&srw[t][0])[c4] =
            *(const float4*)(rw + base + (size_t)t * DD + (c4 << 2));
    }
    __syncthreads();
    // thread owns 2 rows x 4 cols
    int t0 = (tid >> 4) << 1;
    int v0 = (tid & 15) << 2;
    float4 acc0 = {0.f,0.f,0.f,0.f}, acc1 = {0.f,0.f,0.f,0.f};
#pragma unroll 4
    for (int c = 0; c < KK; c++) {
        float4 sv4 = *(const float4*)&sst[c][v0];
        float r0 = srw[t0][c], r1 = srw[t0 + 1][c];
        acc0.x += r0 * sv4.x; acc0.y += r0 * sv4.y;
        acc0.z += r0 * sv4.z; acc0.w += r0 * sv4.w;
        acc1.x += r1 * sv4.x; acc1.y += r1 * sv4.y;
        acc1.z += r1 * sv4.z; acc1.w += r1 * sv4.w;
    }
    float4* o0 = (float4*)(att + base + (size_t)t0 * DD + v0);
    float4* o1 = (float4*)(att + base + (size_t)(t0 + 1) * DD + v0);
    float4 p0 = *o0, p1 = *o1;
    p0.x += acc0.x; p0.y += acc0.y; p0.z += acc0.z; p0.w += acc0.w;
    p1.x += acc1.x; p1.y += acc1.y; p1.z += acc1.z; p1.w += acc1.w;
    *o0 = p0; *o1 = p1;
}

// ---------------- group-norm (per head) + gate ------------------------------
__global__ __launch_bounds__(256) void gnorm_gate(
    const float* __restrict__ att, const float* __restrict__ gate,
    const float* __restrict__ lnw, const float* __restrict__ lnb,
    float* __restrict__ y)
{
    int token = blockIdx.x, tid = threadIdx.x;
    size_t base = (size_t)token * DD + tid * 4;
    float4 v4 = *(const float4*)(att + base);
    float s  = v4.x + v4.y + v4.z + v4.w;
    float ss = v4.x * v4.x + v4.y * v4.y + v4.z * v4.z + v4.w * v4.w;
#pragma unroll
    for (int o = 1; o < 16; o <<= 1) {
        s  += __shfl_xor_sync(0xffffffffu, s,  o);
        ss += __shfl_xor_sync(0xffffffffu, ss, o);
    }
    float mean = s * (1.f / KK);
    float var  = ss * (1.f / KK) - mean * mean;
    float rstd = rsqrtf(var + LN_EPS);
    float4 g4 = *(const float4*)(gate + base);
    float4 w4 = *(const float4*)(lnw + tid * 4);
    float4 b4 = *(const float4*)(lnb + tid * 4);
    float4 o4;
    o4.x = ((v4.x - mean) * rstd * w4.x + b4.x) * g4.x;
    o4.y = ((v4.y - mean) * rstd * w4.y + b4.y) * g4.y;
    o4.z = ((v4.z - mean) * rstd * w4.z + b4.z) * g4.z;
    o4.w = ((v4.w - mean) * rstd * w4.w + b4.w) * g4.w;
    *(float4*)(y + base) = o4;
}

// ---------------- launch ----------------------------------------------------
extern "C" void kernel_launch(void* const* d_in, const int* in_sizes, int n_in,
                              void* d_out, int out_size)
{
    const float* x     = (const float*)d_in[0];
    const float* tmx   = (const float*)d_in[1];
    const float* tmw   = (const float*)d_in[2];
    const float* tmk   = (const float*)d_in[3];
    const float* tmv   = (const float*)d_in[4];
    const float* tmr   = (const float*)d_in[5];
    const float* tmg   = (const float*)d_in[6];
    const float* w1    = (const float*)d_in[7];
    const float* w2    = (const float*)d_in[8];
    const float* tdec  = (const float*)d_in[9];
    const float* dw1   = (const float*)d_in[10];
    const float* dw2   = (const float*)d_in[11];
    const float* faaaa = (const float*)d_in[12];
    const float* Wr    = (const float*)d_in[13];
    const float* Wk    = (const float*)d_in[14];
    const float* Wv    = (const float*)d_in[15];
    const float* Wg    = (const float*)d_in[16];
    const float* Wo    = (const float*)d_in[17];
    const float* lnw   = (const float*)d_in[18];
    const float* lnb   = (const float*)d_in[19];
    float* out = (float*)d_out;

    float *p_xx, *p_xmix, *p_xxx, *p_xw, *p_xk, *p_xv, *p_xr, *p_xg;
    float *p_r, *p_k, *p_v, *p_gate, *p_w, *p_t1, *p_rw, *p_att, *p_yn;
    float *p_wkvc, *p_states, *p_expws;
    cudaGetSymbolAddress((void**)&p_xx,    g_xx);
    cudaGetSymbolAddress((void**)&p_xmix,  g_xmix);
    cudaGetSymbolAddress((void**)&p_xxx,   g_xxx);
    cudaGetSymbolAddress((void**)&p_xw,    g_xw);
    cudaGetSymbolAddress((void**)&p_xk,    g_xk);
    cudaGetSymbolAddress((void**)&p_xv,    g_xv);
    cudaGetSymbolAddress((void**)&p_xr,    g_xr);
    cudaGetSymbolAddress((void**)&p_xg,    g_xg);
    cudaGetSymbolAddress((void**)&p_r,     g_r);
    cudaGetSymbolAddress((void**)&p_k,     g_k);
    cudaGetSymbolAddress((void**)&p_v,     g_v);
    cudaGetSymbolAddress((void**)&p_gate,  g_gate);
    cudaGetSymbolAddress((void**)&p_w,     g_w);
    cudaGetSymbolAddress((void**)&p_t1,    g_t1);
    cudaGetSymbolAddress((void**)&p_rw,    g_rw);
    cudaGetSymbolAddress((void**)&p_att,   g_att);
    cudaGetSymbolAddress((void**)&p_yn,    g_yn);
    cudaGetSymbolAddress((void**)&p_wkvc,  g_wkvc);
    cudaGetSymbolAddress((void**)&p_states,g_states);
    cudaGetSymbolAddress((void**)&p_expws, g_expws);

    // 1. token shift + mix input
    prep_kernel<<<(BT * DD) / 256, 256>>>(x, tmx, p_xx, p_xmix);
    // 2. xxx = tanh(xmix @ W1)   (8192 x 160 x 1024)
    gemm_tf32<1><<<dim3(2, 64), 256>>>(p_xmix, w1, p_xxx, BT, 160, DD, nullptr);
    // 3. five branch inputs
    branch_mix<<<dim3(BT / 16, 4), 256>>>(x, p_xx, p_xxx, w2,
                                          tmw, tmk, tmv, tmr, tmg,
                                          p_xw, p_xk, p_xv, p_xr, p_xg);
    // 4. batched: r/k/v projections, gate (silu), decay LoRA stage 1 (tanh)
    BatchArgs ba;
    ba.A[0] = p_xr; ba.B[0] = Wr;  ba.C[0] = p_r;    ba.N[0] = DD; ba.epi[0] = 0;
    ba.A[1] = p_xk; ba.B[1] = Wk;  ba.C[1] = p_k;    ba.N[1] = DD; ba.epi[1] = 0;
    ba.A[2] = p_xv; ba.B[2] = Wv;  ba.C[2] = p_v;    ba.N[2] = DD; ba.epi[2] = 0;
    ba.A[3] = p_xg; ba.B[3] = Wg;  ba.C[3] = p_gate; ba.N[3] = DD; ba.epi[3] = 2;
    ba.A[4] = p_xw; ba.B[4] = dw1; ba.C[4] = p_t1;   ba.N[4] = 64; ba.epi[4] = 1;
    gemm_tf32_batch<<<dim3(8, 64, 5), 256>>>(ba);
    // 5. w = -exp(time_decay + t1 @ dw2)
    gemm_tf32<3><<<dim3(8, 64), 256>>>(p_t1, dw2, p_w, BT, DD, 64, tdec);
    // 6. WKV
    wkv_chunk<<<NBH * NCH, 256>>>(p_r, p_k, p_v, p_w, faaaa,
                                  p_rw, p_att, p_wkvc, p_expws);
    wkv_scan<<<NBH, 1024>>>(p_wkvc, p_expws, p_states);
    wkv_state_out<<<NBH * NCH, 256>>>(p_rw, p_states, p_att);
    // 7. group-norm + gate, then output projection
    gnorm_gate<<<BT, 256>>>(p_att, p_gate, lnw, lnb, p_yn);
    gemm_tf32<0><<<dim3(8, 64), 256>>>(p_yn, Wo, out, BT, DD, DD, nullptr);
}